// round 1
// baseline (speedup 1.0000x reference)
#include <cuda_runtime.h>
#include <cstddef>

// Problem constants
#define Bc 4
#define Lc 512
#define Dc 256

constexpr int TILE   = 32;                    // score tile edge
constexpr int NT     = Lc / TILE;             // 16 tiles per dim
constexpr int NPAIR  = NT * (NT + 1) / 2;     // 136 (ti <= tj)
constexpr int SCORE_SMEM = (2 * TILE * Dc + Dc) * (int)sizeof(float); // 66560 B

__device__ __forceinline__ float tanh_fast(float x) {
    float y;
    asm("tanh.approx.f32 %0, %1;" : "=f"(y) : "f"(x));
    return y;
}

// ---------------------------------------------------------------------------
// Kernel 1: pairwise tanh scores, exploiting symmetry (ti <= tj tiles only).
// Block: 256 threads = 16x16, each thread computes a 2x2 micro-tile of the
// 32x32 score tile. Shared: Hi tile (32x256), Hj tile (32x256), w (256).
// Per-thread d-rotation makes all shared loads bank-conflict-free.
// ---------------------------------------------------------------------------
__global__ __launch_bounds__(256) void scores_kernel(
    const float* __restrict__ H, const float* __restrict__ w,
    const float* __restrict__ bias_p, float* __restrict__ S)
{
    extern __shared__ float sh[];
    float* His = sh;                 // 32*256
    float* Hjs = sh + TILE * Dc;     // 32*256
    float* ws  = sh + 2 * TILE * Dc; // 256

    const int blk = blockIdx.x;
    const int b = blk / NPAIR;
    int p = blk % NPAIR;
    int ti = 0;
    while (p >= NT - ti) { p -= NT - ti; ti++; }
    const int tj = ti + p;

    const int tid = threadIdx.x;

    // Load H tiles as float4 (2048 float4 per tile, 8 per thread)
    const float4* Hi4 = (const float4*)(H + ((size_t)b * Lc + (size_t)ti * TILE) * Dc);
    const float4* Hj4 = (const float4*)(H + ((size_t)b * Lc + (size_t)tj * TILE) * Dc);
    float4* His4 = (float4*)His;
    float4* Hjs4 = (float4*)Hjs;
#pragma unroll
    for (int k = 0; k < 8; k++) {
        His4[tid + k * 256] = Hi4[tid + k * 256];
        Hjs4[tid + k * 256] = Hj4[tid + k * 256];
    }
    ws[tid] = w[tid];
    __syncthreads();

    const int ty = tid >> 4;     // 0..15
    const int tx = tid & 15;     // 0..15

    const float* hiA = His + (size_t)ty * Dc;
    const float* hiB = His + (size_t)(ty + 16) * Dc;
    const float* hjA = Hjs + (size_t)tx * Dc;
    const float* hjB = Hjs + (size_t)(tx + 16) * Dc;

    float a00 = 0.f, a01 = 0.f, a10 = 0.f, a11 = 0.f;

    // d-rotation: within a warp (ty in {w0,w0+1}, tx 0..15) bank = (dd+2tx+ty)&31
    // -> 32 distinct banks for every shared stream.
    const int doff = (2 * tx + ty) & (Dc - 1);

#pragma unroll 4
    for (int dd = 0; dd < Dc; dd++) {
        const int d = (dd + doff) & (Dc - 1);
        const float wv = ws[d];
        const float h0 = hiA[d];
        const float h1 = hiB[d];
        const float g0 = hjA[d];
        const float g1 = hjB[d];
        a00 = fmaf(tanh_fast(h0 + g0), wv, a00);
        a01 = fmaf(tanh_fast(h0 + g1), wv, a01);
        a10 = fmaf(tanh_fast(h1 + g0), wv, a10);
        a11 = fmaf(tanh_fast(h1 + g1), wv, a11);
    }

    const float bias = *bias_p;
    a00 += bias; a01 += bias; a10 += bias; a11 += bias;

    const int gi0 = ti * TILE + ty, gi1 = gi0 + 16;
    const int gj0 = tj * TILE + tx, gj1 = gj0 + 16;
    float* Sb = S + (size_t)b * Lc * Lc;

    Sb[(size_t)gi0 * Lc + gj0] = a00;
    Sb[(size_t)gi0 * Lc + gj1] = a01;
    Sb[(size_t)gi1 * Lc + gj0] = a10;
    Sb[(size_t)gi1 * Lc + gj1] = a11;
    if (ti != tj) {  // mirror (scores are symmetric)
        Sb[(size_t)gj0 * Lc + gi0] = a00;
        Sb[(size_t)gj1 * Lc + gi0] = a01;
        Sb[(size_t)gj0 * Lc + gi1] = a10;
        Sb[(size_t)gj1 * Lc + gi1] = a11;
    }
}

// ---------------------------------------------------------------------------
// Kernel 2: in-place row softmax over the last axis (rows of length 512).
// One block (128 threads) per row; 4 elements per thread (float4).
// ---------------------------------------------------------------------------
__global__ __launch_bounds__(128) void softmax_kernel(float* __restrict__ S)
{
    const int row = blockIdx.x;              // b*L + i
    float4* p = (float4*)(S + (size_t)row * Lc);
    const int tid = threadIdx.x;
    const int lane = tid & 31;
    const int wid = tid >> 5;

    float4 v = p[tid];

    float m = fmaxf(fmaxf(v.x, v.y), fmaxf(v.z, v.w));
#pragma unroll
    for (int o = 16; o > 0; o >>= 1)
        m = fmaxf(m, __shfl_xor_sync(0xffffffffu, m, o));

    __shared__ float redm[4];
    __shared__ float reds[4];
    if (lane == 0) redm[wid] = m;
    __syncthreads();
    m = fmaxf(fmaxf(redm[0], redm[1]), fmaxf(redm[2], redm[3]));

    float4 e;
    e.x = __expf(v.x - m);
    e.y = __expf(v.y - m);
    e.z = __expf(v.z - m);
    e.w = __expf(v.w - m);

    float s = e.x + e.y + e.z + e.w;
#pragma unroll
    for (int o = 16; o > 0; o >>= 1)
        s += __shfl_xor_sync(0xffffffffu, s, o);
    if (lane == 0) reds[wid] = s;
    __syncthreads();
    s = reds[0] + reds[1] + reds[2] + reds[3];

    const float inv = 1.0f / s;
    e.x *= inv; e.y *= inv; e.z *= inv; e.w *= inv;
    p[tid] = e;
}

// ---------------------------------------------------------------------------
// Kernel 3: r = alpha @ H   (per batch: [L,L] @ [L,D] -> [L,D])
// Block: 256 threads (one per d), handles 8 consecutive i-rows; alpha tile
// staged in shared, H rows streamed (coalesced, L2-resident).
// ---------------------------------------------------------------------------
constexpr int IT = 8;    // i rows per block
constexpr int JT = 256;  // j chunk

__global__ __launch_bounds__(256) void r_kernel(
    const float* __restrict__ A, const float* __restrict__ H,
    float* __restrict__ R)
{
    const int b  = blockIdx.x / (Lc / IT);
    const int it = blockIdx.x % (Lc / IT);
    const int tid = threadIdx.x;

    const float* Ab = A + ((size_t)b * Lc + (size_t)it * IT) * Lc;
    const float* Hb = H + (size_t)b * Lc * Dc;

    __shared__ float As[IT][JT];
    float acc[IT];
#pragma unroll
    for (int r = 0; r < IT; r++) acc[r] = 0.f;

    for (int jc = 0; jc < Lc; jc += JT) {
        __syncthreads();
#pragma unroll
        for (int r = 0; r < IT; r++)
            As[r][tid] = Ab[(size_t)r * Lc + jc + tid];
        __syncthreads();

#pragma unroll 4
        for (int jj = 0; jj < JT; jj++) {
            const float h = Hb[(size_t)(jc + jj) * Dc + tid];
#pragma unroll
            for (int r = 0; r < IT; r++)
                acc[r] = fmaf(As[r][jj], h, acc[r]);
        }
    }

    float* Rb = R + ((size_t)b * Lc + (size_t)it * IT) * Dc;
#pragma unroll
    for (int r = 0; r < IT; r++)
        Rb[(size_t)r * Dc + tid] = acc[r];
}

// ---------------------------------------------------------------------------
extern "C" void kernel_launch(void* const* d_in, const int* in_sizes, int n_in,
                              void* d_out, int out_size)
{
    const float* H    = (const float*)d_in[0];
    const float* w    = (const float*)d_in[1];
    const float* bias = (const float*)d_in[2];

    float* R     = (float*)d_out;                              // (B, L, D)
    float* Alpha = (float*)d_out + (size_t)Bc * Lc * Dc;       // (B, L, L)

    cudaFuncSetAttribute(scores_kernel,
                         cudaFuncAttributeMaxDynamicSharedMemorySize,
                         SCORE_SMEM);

    scores_kernel<<<Bc * NPAIR, 256, SCORE_SMEM>>>(H, w, bias, Alpha);
    softmax_kernel<<<Bc * Lc, 128>>>(Alpha);
    r_kernel<<<Bc * (Lc / IT), 256>>>(Alpha, H, R);
}

// round 2
// speedup vs baseline: 1.0805x; 1.0805x over previous
#include <cuda_runtime.h>
#include <cstddef>

#define Bc 4
#define Lc 512
#define Dc 256

constexpr int TILE  = 32;
constexpr int NT    = Lc / TILE;          // 16
constexpr int NPAIR = NT * (NT + 1) / 2;  // 136
constexpr int CH    = 64;                 // d-chunk
constexpr int NCH   = Dc / CH;            // 4
constexpr int STR   = CH + 4;             // 68 floats/row: conflict-free & float4-aligned

__device__ __forceinline__ float tanh_fast(float x) {
    float y;
    asm("tanh.approx.f32 %0, %1;" : "=f"(y) : "f"(x));
    return y;
}

// ---------------------------------------------------------------------------
// Kernel 1: pairwise tanh scores, symmetric tiles (ti <= tj), d-chunked smem
// so 6-8 blocks/SM fit -> whole grid runs in ONE wave. All shared traffic is
// float4, statically indexed (no per-iteration integer math).
// ---------------------------------------------------------------------------
__global__ __launch_bounds__(256) void scores_kernel(
    const float* __restrict__ H, const float* __restrict__ w,
    const float* __restrict__ bias_p, float* __restrict__ S)
{
    __shared__ float His[TILE * STR];
    __shared__ float Hjs[TILE * STR];
    __shared__ float ws[Dc];

    const int blk = blockIdx.x;
    const int b = blk / NPAIR;
    int p = blk % NPAIR;
    int ti = 0;
    while (p >= NT - ti) { p -= NT - ti; ti++; }
    const int tj = ti + p;

    const int tid = threadIdx.x;
    ws[tid] = w[tid];

    const int ty = tid >> 4;   // 0..15
    const int tx = tid & 15;   // 0..15

    const float4* Hi4 = (const float4*)(H + ((size_t)b * Lc + (size_t)ti * TILE) * Dc);
    const float4* Hj4 = (const float4*)(H + ((size_t)b * Lc + (size_t)tj * TILE) * Dc);
    float4* His4 = (float4*)His;
    float4* Hjs4 = (float4*)Hjs;

    float a00 = 0.f, a01 = 0.f, a10 = 0.f, a11 = 0.f;

    for (int c = 0; c < NCH; c++) {
        __syncthreads();
        // Load 64-wide d-chunk of both 32-row tiles; rows ty and ty+16,
        // float4 column tx within the chunk. Coalesced global, conflict-free shared.
        His4[ty * (STR/4) + tx]        = Hi4[ty * (Dc/4) + c * (CH/4) + tx];
        His4[(ty+16) * (STR/4) + tx]   = Hi4[(ty+16) * (Dc/4) + c * (CH/4) + tx];
        Hjs4[ty * (STR/4) + tx]        = Hj4[ty * (Dc/4) + c * (CH/4) + tx];
        Hjs4[(ty+16) * (STR/4) + tx]   = Hj4[(ty+16) * (Dc/4) + c * (CH/4) + tx];
        __syncthreads();

        const float4* hiA = (const float4*)(His + (size_t)ty * STR);
        const float4* hiB = (const float4*)(His + (size_t)(ty + 16) * STR);
        const float4* hjA = (const float4*)(Hjs + (size_t)tx * STR);
        const float4* hjB = (const float4*)(Hjs + (size_t)(tx + 16) * STR);
        const float4* w4  = (const float4*)(ws + c * CH);

#pragma unroll
        for (int g = 0; g < CH / 4; g++) {
            const float4 wv = w4[g];
            const float4 hp = hiA[g];
            const float4 hq = hiB[g];
            const float4 gu = hjA[g];
            const float4 gv = hjB[g];

            a00 = fmaf(tanh_fast(hp.x + gu.x), wv.x, a00);
            a01 = fmaf(tanh_fast(hp.x + gv.x), wv.x, a01);
            a10 = fmaf(tanh_fast(hq.x + gu.x), wv.x, a10);
            a11 = fmaf(tanh_fast(hq.x + gv.x), wv.x, a11);

            a00 = fmaf(tanh_fast(hp.y + gu.y), wv.y, a00);
            a01 = fmaf(tanh_fast(hp.y + gv.y), wv.y, a01);
            a10 = fmaf(tanh_fast(hq.y + gu.y), wv.y, a10);
            a11 = fmaf(tanh_fast(hq.y + gv.y), wv.y, a11);

            a00 = fmaf(tanh_fast(hp.z + gu.z), wv.z, a00);
            a01 = fmaf(tanh_fast(hp.z + gv.z), wv.z, a01);
            a10 = fmaf(tanh_fast(hq.z + gu.z), wv.z, a10);
            a11 = fmaf(tanh_fast(hq.z + gv.z), wv.z, a11);

            a00 = fmaf(tanh_fast(hp.w + gu.w), wv.w, a00);
            a01 = fmaf(tanh_fast(hp.w + gv.w), wv.w, a01);
            a10 = fmaf(tanh_fast(hq.w + gu.w), wv.w, a10);
            a11 = fmaf(tanh_fast(hq.w + gv.w), wv.w, a11);
        }
    }

    const float bias = *bias_p;
    a00 += bias; a01 += bias; a10 += bias; a11 += bias;

    const int gi0 = ti * TILE + ty, gi1 = gi0 + 16;
    const int gj0 = tj * TILE + tx, gj1 = gj0 + 16;
    float* Sb = S + (size_t)b * Lc * Lc;

    Sb[(size_t)gi0 * Lc + gj0] = a00;
    Sb[(size_t)gi0 * Lc + gj1] = a01;
    Sb[(size_t)gi1 * Lc + gj0] = a10;
    Sb[(size_t)gi1 * Lc + gj1] = a11;
    if (ti != tj) {  // mirror (scores are symmetric)
        Sb[(size_t)gj0 * Lc + gi0] = a00;
        Sb[(size_t)gj1 * Lc + gi0] = a01;
        Sb[(size_t)gj0 * Lc + gi1] = a10;
        Sb[(size_t)gj1 * Lc + gi1] = a11;
    }
}

// ---------------------------------------------------------------------------
// Kernel 2 (fused): softmax over each score row + r = alpha @ H.
// Block = 256 threads / 8 warps; warp w owns row w of the 8-row i-tile:
// softmax is pure warp shuffles (no block barrier), normalized alpha goes to
// smem AND to the alpha output, then the block does the 8x256 GEMM slice
// reading alpha from smem (broadcast float4) and H from L2.
// ---------------------------------------------------------------------------
constexpr int IT = 8;

__global__ __launch_bounds__(256) void softmax_r_kernel(
    float* __restrict__ Alpha, const float* __restrict__ H,
    float* __restrict__ R)
{
    __shared__ float As[IT][Lc];

    const int b     = blockIdx.x / (Lc / IT);
    const int itile = blockIdx.x % (Lc / IT);
    const int tid   = threadIdx.x;
    const int warp  = tid >> 5;
    const int lane  = tid & 31;

    float* Ab = Alpha + ((size_t)b * Lc + (size_t)itile * IT) * Lc;
    float4* rowg = (float4*)(Ab + (size_t)warp * Lc);
    float4* rows = (float4*)As[warp];

    // ---- softmax of this warp's row (512 elems = 4 float4 per lane) ----
    float4 v[4];
    float m = -3.0e38f;
#pragma unroll
    for (int t = 0; t < 4; t++) {
        v[t] = rowg[lane + 32 * t];
        m = fmaxf(m, fmaxf(fmaxf(v[t].x, v[t].y), fmaxf(v[t].z, v[t].w)));
    }
#pragma unroll
    for (int o = 16; o > 0; o >>= 1)
        m = fmaxf(m, __shfl_xor_sync(0xffffffffu, m, o));

    float s = 0.f;
#pragma unroll
    for (int t = 0; t < 4; t++) {
        v[t].x = __expf(v[t].x - m);
        v[t].y = __expf(v[t].y - m);
        v[t].z = __expf(v[t].z - m);
        v[t].w = __expf(v[t].w - m);
        s += (v[t].x + v[t].y) + (v[t].z + v[t].w);
    }
#pragma unroll
    for (int o = 16; o > 0; o >>= 1)
        s += __shfl_xor_sync(0xffffffffu, s, o);

    const float inv = 1.0f / s;
#pragma unroll
    for (int t = 0; t < 4; t++) {
        v[t].x *= inv; v[t].y *= inv; v[t].z *= inv; v[t].w *= inv;
        rows[lane + 32 * t] = v[t];   // smem for GEMM
        rowg[lane + 32 * t] = v[t];   // alpha output
    }
    __syncthreads();

    // ---- r tile: acc[r] = sum_j As[r][j] * H[b][j][tid] ----
    const float* Hb = H + (size_t)b * Lc * Dc;
    float acc[IT];
#pragma unroll
    for (int r = 0; r < IT; r++) acc[r] = 0.f;

#pragma unroll 2
    for (int jj = 0; jj < Lc; jj += 4) {
        float4 a[IT];
#pragma unroll
        for (int r = 0; r < IT; r++)
            a[r] = *(const float4*)(&As[r][jj]);

        const float h0 = Hb[(size_t)(jj + 0) * Dc + tid];
        const float h1 = Hb[(size_t)(jj + 1) * Dc + tid];
        const float h2 = Hb[(size_t)(jj + 2) * Dc + tid];
        const float h3 = Hb[(size_t)(jj + 3) * Dc + tid];

#pragma unroll
        for (int r = 0; r < IT; r++) {
            acc[r] = fmaf(a[r].x, h0, acc[r]);
            acc[r] = fmaf(a[r].y, h1, acc[r]);
            acc[r] = fmaf(a[r].z, h2, acc[r]);
            acc[r] = fmaf(a[r].w, h3, acc[r]);
        }
    }

    float* Rb = R + ((size_t)b * Lc + (size_t)itile * IT) * Dc;
#pragma unroll
    for (int r = 0; r < IT; r++)
        Rb[(size_t)r * Dc + tid] = acc[r];
}

// ---------------------------------------------------------------------------
extern "C" void kernel_launch(void* const* d_in, const int* in_sizes, int n_in,
                              void* d_out, int out_size)
{
    const float* H    = (const float*)d_in[0];
    const float* w    = (const float*)d_in[1];
    const float* bias = (const float*)d_in[2];

    float* R     = (float*)d_out;                          // (B, L, D)
    float* Alpha = (float*)d_out + (size_t)Bc * Lc * Dc;   // (B, L, L)

    scores_kernel<<<Bc * NPAIR, 256>>>(H, w, bias, Alpha);
    softmax_r_kernel<<<Bc * (Lc / IT), 256>>>(Alpha, H, R);
}

// round 4
// speedup vs baseline: 1.1684x; 1.0814x over previous
#include <cuda_runtime.h>
#include <cstddef>

#define Bc 4
#define Lc 512
#define Dc 256

constexpr int TILE  = 32;
constexpr int NT    = Lc / TILE;          // 16
constexpr int NPAIR = NT * (NT + 1) / 2;  // 136
constexpr int CH    = 64;                 // d-chunk (scores)
constexpr int NCH   = Dc / CH;            // 4
constexpr int STR   = CH + 4;             // 68: conflict-free & float4-aligned

__device__ __forceinline__ float tanh_fast(float x) {
    float y;
    asm("tanh.approx.f32 %0, %1;" : "=f"(y) : "f"(x));
    return y;
}

__device__ __forceinline__ void cp16(float* s, const float* g) {
    unsigned saddr = (unsigned)__cvta_generic_to_shared(s);
    asm volatile("cp.async.cg.shared.global [%0], [%1], 16;" :: "r"(saddr), "l"(g));
}

// ---------------------------------------------------------------------------
// Kernel 1: pairwise tanh scores, symmetric tiles (ti <= tj), d-chunked smem.
// ---------------------------------------------------------------------------
__global__ __launch_bounds__(256) void scores_kernel(
    const float* __restrict__ H, const float* __restrict__ w,
    const float* __restrict__ bias_p, float* __restrict__ S)
{
    __shared__ float His[TILE * STR];
    __shared__ float Hjs[TILE * STR];
    __shared__ float ws[Dc];

    const int blk = blockIdx.x;
    const int b = blk / NPAIR;
    int p = blk % NPAIR;
    int ti = 0;
    while (p >= NT - ti) { p -= NT - ti; ti++; }
    const int tj = ti + p;

    const int tid = threadIdx.x;
    ws[tid] = w[tid];

    const int ty = tid >> 4;   // 0..15
    const int tx = tid & 15;   // 0..15

    const float4* Hi4 = (const float4*)(H + ((size_t)b * Lc + (size_t)ti * TILE) * Dc);
    const float4* Hj4 = (const float4*)(H + ((size_t)b * Lc + (size_t)tj * TILE) * Dc);
    float4* His4 = (float4*)His;
    float4* Hjs4 = (float4*)Hjs;

    float a00 = 0.f, a01 = 0.f, a10 = 0.f, a11 = 0.f;

    for (int c = 0; c < NCH; c++) {
        __syncthreads();
        His4[ty * (STR/4) + tx]        = Hi4[ty * (Dc/4) + c * (CH/4) + tx];
        His4[(ty+16) * (STR/4) + tx]   = Hi4[(ty+16) * (Dc/4) + c * (CH/4) + tx];
        Hjs4[ty * (STR/4) + tx]        = Hj4[ty * (Dc/4) + c * (CH/4) + tx];
        Hjs4[(ty+16) * (STR/4) + tx]   = Hj4[(ty+16) * (Dc/4) + c * (CH/4) + tx];
        __syncthreads();

        const float4* hiA = (const float4*)(His + (size_t)ty * STR);
        const float4* hiB = (const float4*)(His + (size_t)(ty + 16) * STR);
        const float4* hjA = (const float4*)(Hjs + (size_t)tx * STR);
        const float4* hjB = (const float4*)(Hjs + (size_t)(tx + 16) * STR);
        const float4* w4  = (const float4*)(ws + c * CH);

#pragma unroll
        for (int g = 0; g < CH / 4; g++) {
            const float4 wv = w4[g];
            const float4 hp = hiA[g];
            const float4 hq = hiB[g];
            const float4 gu = hjA[g];
            const float4 gv = hjB[g];

            a00 = fmaf(tanh_fast(hp.x + gu.x), wv.x, a00);
            a01 = fmaf(tanh_fast(hp.x + gv.x), wv.x, a01);
            a10 = fmaf(tanh_fast(hq.x + gu.x), wv.x, a10);
            a11 = fmaf(tanh_fast(hq.x + gv.x), wv.x, a11);

            a00 = fmaf(tanh_fast(hp.y + gu.y), wv.y, a00);
            a01 = fmaf(tanh_fast(hp.y + gv.y), wv.y, a01);
            a10 = fmaf(tanh_fast(hq.y + gu.y), wv.y, a10);
            a11 = fmaf(tanh_fast(hq.y + gv.y), wv.y, a11);

            a00 = fmaf(tanh_fast(hp.z + gu.z), wv.z, a00);
            a01 = fmaf(tanh_fast(hp.z + gv.z), wv.z, a01);
            a10 = fmaf(tanh_fast(hq.z + gu.z), wv.z, a10);
            a11 = fmaf(tanh_fast(hq.z + gv.z), wv.z, a11);

            a00 = fmaf(tanh_fast(hp.w + gu.w), wv.w, a00);
            a01 = fmaf(tanh_fast(hp.w + gv.w), wv.w, a01);
            a10 = fmaf(tanh_fast(hq.w + gu.w), wv.w, a10);
            a11 = fmaf(tanh_fast(hq.w + gv.w), wv.w, a11);
        }
    }

    const float bias = *bias_p;
    a00 += bias; a01 += bias; a10 += bias; a11 += bias;

    const int gi0 = ti * TILE + ty, gi1 = gi0 + 16;
    const int gj0 = tj * TILE + tx, gj1 = gj0 + 16;
    float* Sb = S + (size_t)b * Lc * Lc;

    Sb[(size_t)gi0 * Lc + gj0] = a00;
    Sb[(size_t)gi0 * Lc + gj1] = a01;
    Sb[(size_t)gi1 * Lc + gj0] = a10;
    Sb[(size_t)gi1 * Lc + gj1] = a11;
    if (ti != tj) {
        Sb[(size_t)gj0 * Lc + gi0] = a00;
        Sb[(size_t)gj1 * Lc + gi0] = a01;
        Sb[(size_t)gj0 * Lc + gi1] = a10;
        Sb[(size_t)gj1 * Lc + gi1] = a11;
    }
}

// ---------------------------------------------------------------------------
// Kernel 2 (fused): row softmax + r = alpha @ H, with H staged through smem
// via a cp.async double-buffered pipeline (32-j x 256-d chunks).
// Inner loop is pure LDS + FFMA: alpha reads are warp broadcasts, H reads are
// 32-consecutive-float conflict-free LDS.
// ---------------------------------------------------------------------------
constexpr int IT  = 8;
constexpr int JC  = 32;                               // j rows per H chunk
constexpr int NJC = Lc / JC;                          // 16 chunks
constexpr int SMEM_R = (IT * Lc + 2 * JC * Dc) * (int)sizeof(float); // 81920

__global__ __launch_bounds__(256) void softmax_r_kernel(
    float* __restrict__ Alpha, const float* __restrict__ H,
    float* __restrict__ R)
{
    extern __shared__ float sh[];
    float* As  = sh;                    // IT * 512
    float* Hs0 = sh + IT * Lc;          // 32 * 256
    float* Hs1 = Hs0 + JC * Dc;         // 32 * 256

    const int b     = blockIdx.x / (Lc / IT);
    const int itile = blockIdx.x % (Lc / IT);
    const int tid   = threadIdx.x;
    const int warp  = tid >> 5;
    const int lane  = tid & 31;

    const float* Hb = H + (size_t)b * Lc * Dc;

    // Prefetch H chunk 0 while doing softmax.
#pragma unroll
    for (int k = 0; k < 8; k++) {
        const int v = tid + (k << 8);       // float4 index in 32x256 chunk
        cp16(Hs0 + v * 4, Hb + (size_t)v * 4);
    }
    asm volatile("cp.async.commit_group;");

    // ---- softmax of this warp's row (512 elems = 4 float4 per lane) ----
    float* Ab = Alpha + ((size_t)b * Lc + (size_t)itile * IT) * Lc;
    float4* rowg = (float4*)(Ab + (size_t)warp * Lc);
    float4* rows = (float4*)(As + (size_t)warp * Lc);

    float4 v[4];
    float m = -3.0e38f;
#pragma unroll
    for (int t = 0; t < 4; t++) {
        v[t] = rowg[lane + 32 * t];
        m = fmaxf(m, fmaxf(fmaxf(v[t].x, v[t].y), fmaxf(v[t].z, v[t].w)));
    }
#pragma unroll
    for (int o = 16; o > 0; o >>= 1)
        m = fmaxf(m, __shfl_xor_sync(0xffffffffu, m, o));

    float s = 0.f;
#pragma unroll
    for (int t = 0; t < 4; t++) {
        v[t].x = __expf(v[t].x - m);
        v[t].y = __expf(v[t].y - m);
        v[t].z = __expf(v[t].z - m);
        v[t].w = __expf(v[t].w - m);
        s += (v[t].x + v[t].y) + (v[t].z + v[t].w);
    }
#pragma unroll
    for (int o = 16; o > 0; o >>= 1)
        s += __shfl_xor_sync(0xffffffffu, s, o);

    const float inv = 1.0f / s;
#pragma unroll
    for (int t = 0; t < 4; t++) {
        v[t].x *= inv; v[t].y *= inv; v[t].z *= inv; v[t].w *= inv;
        rows[lane + 32 * t] = v[t];   // smem for GEMM
        rowg[lane + 32 * t] = v[t];   // alpha output
    }

    float acc[IT];
#pragma unroll
    for (int r = 0; r < IT; r++) acc[r] = 0.f;

    // ---- pipelined GEMM over 16 H chunks ----
    for (int c = 0; c < NJC; c++) {
        float* cur = (c & 1) ? Hs1 : Hs0;
        float* nxt = (c & 1) ? Hs0 : Hs1;

        if (c < NJC - 1) {
            const float* src = Hb + (size_t)(c + 1) * JC * Dc;
#pragma unroll
            for (int k = 0; k < 8; k++) {
                const int vv = tid + (k << 8);
                cp16(nxt + vv * 4, src + (size_t)vv * 4);
            }
            asm volatile("cp.async.commit_group;");
            asm volatile("cp.async.wait_group 1;");
        } else {
            asm volatile("cp.async.wait_group 0;");
        }
        __syncthreads();   // chunk c visible to all; also protects As on c==0

#pragma unroll
        for (int jj = 0; jj < JC; jj += 4) {
            float4 a[IT];
#pragma unroll
            for (int r = 0; r < IT; r++)
                a[r] = *(const float4*)(As + (size_t)r * Lc + c * JC + jj);

            const float h0 = cur[(jj + 0) * Dc + tid];
            const float h1 = cur[(jj + 1) * Dc + tid];
            const float h2 = cur[(jj + 2) * Dc + tid];
            const float h3 = cur[(jj + 3) * Dc + tid];

#pragma unroll
            for (int r = 0; r < IT; r++) {
                acc[r] = fmaf(a[r].x, h0, acc[r]);
                acc[r] = fmaf(a[r].y, h1, acc[r]);
                acc[r] = fmaf(a[r].z, h2, acc[r]);
                acc[r] = fmaf(a[r].w, h3, acc[r]);
            }
        }
        __syncthreads();   // all warps done with 'cur' before it is refilled
    }

    float* Rb = R + ((size_t)b * Lc + (size_t)itile * IT) * Dc;
#pragma unroll
    for (int r = 0; r < IT; r++)
        Rb[(size_t)r * Dc + tid] = acc[r];
}

// ---------------------------------------------------------------------------
extern "C" void kernel_launch(void* const* d_in, const int* in_sizes, int n_in,
                              void* d_out, int out_size)
{
    const float* H    = (const float*)d_in[0];
    const float* w    = (const float*)d_in[1];
    const float* bias = (const float*)d_in[2];

    float* R     = (float*)d_out;                          // (B, L, D)
    float* Alpha = (float*)d_out + (size_t)Bc * Lc * Dc;   // (B, L, L)

    cudaFuncSetAttribute(softmax_r_kernel,
                         cudaFuncAttributeMaxDynamicSharedMemorySize, SMEM_R);

    scores_kernel<<<Bc * NPAIR, 256>>>(H, w, bias, Alpha);
    softmax_r_kernel<<<Bc * (Lc / IT), 256, SMEM_R>>>(Alpha, H, R);
}

// round 5
// speedup vs baseline: 1.2063x; 1.0324x over previous
#include <cuda_runtime.h>
#include <cstddef>

#define Bc 4
#define Lc 512
#define Dc 256

constexpr int TILE  = 32;
constexpr int NT    = Lc / TILE;          // 16
constexpr int NPAIR = NT * (NT + 1) / 2;  // 136
constexpr int CH    = 64;                 // d-chunk (scores)
constexpr int NCH   = Dc / CH;            // 4
constexpr int STR   = CH + 4;             // 68: conflict-free & float4-aligned

// Raw (pre-softmax) scores scratch: 4 MB static device buffer.
__device__ float Sbuf[(size_t)Bc * Lc * Lc];

typedef unsigned long long u64;

__device__ __forceinline__ float tanh_fast(float x) {
    float y;
    asm("tanh.approx.f32 %0, %1;" : "=f"(y) : "f"(x));
    return y;
}

__device__ __forceinline__ void cp16(float* s, const float* g) {
    unsigned saddr = (unsigned)__cvta_generic_to_shared(s);
    asm volatile("cp.async.cg.shared.global [%0], [%1], 16;" :: "r"(saddr), "l"(g));
}

#define FMA2(d, a, b, c) \
    asm("fma.rn.f32x2 %0, %1, %2, %3;" : "=l"(d) : "l"(a), "l"(b), "l"(c))
#define SPLAT2(d, f) \
    asm("mov.b64 %0, {%1, %1};" : "=l"(d) : "f"(f))
#define UNPACK2(lo, hi, p) \
    asm("mov.b64 {%0, %1}, %2;" : "=f"(lo), "=f"(hi) : "l"(p))

// ---------------------------------------------------------------------------
// Kernel 1: pairwise tanh scores -> Sbuf (raw). Also zeroes R (d_out region)
// so the downstream split-j GEMM can accumulate with atomics.
// ---------------------------------------------------------------------------
__global__ __launch_bounds__(256) void scores_kernel(
    const float* __restrict__ H, const float* __restrict__ w,
    const float* __restrict__ bias_p, float* __restrict__ R)
{
    __shared__ float His[TILE * STR];
    __shared__ float Hjs[TILE * STR];
    __shared__ float ws[Dc];

    const int blk = blockIdx.x;
    const int tid = threadIdx.x;

    // Zero the R output region (B*L*D floats = 131072 float4).
    {
        const int u = blk * 256 + tid;
        if (u < (Bc * Lc * Dc) / 4)
            ((float4*)R)[u] = make_float4(0.f, 0.f, 0.f, 0.f);
    }

    const int b = blk / NPAIR;
    int p = blk % NPAIR;
    int ti = 0;
    while (p >= NT - ti) { p -= NT - ti; ti++; }
    const int tj = ti + p;

    ws[tid] = w[tid];

    const int ty = tid >> 4;   // 0..15
    const int tx = tid & 15;   // 0..15

    const float4* Hi4 = (const float4*)(H + ((size_t)b * Lc + (size_t)ti * TILE) * Dc);
    const float4* Hj4 = (const float4*)(H + ((size_t)b * Lc + (size_t)tj * TILE) * Dc);
    float4* His4 = (float4*)His;
    float4* Hjs4 = (float4*)Hjs;

    float a00 = 0.f, a01 = 0.f, a10 = 0.f, a11 = 0.f;

    for (int c = 0; c < NCH; c++) {
        __syncthreads();
        His4[ty * (STR/4) + tx]        = Hi4[ty * (Dc/4) + c * (CH/4) + tx];
        His4[(ty+16) * (STR/4) + tx]   = Hi4[(ty+16) * (Dc/4) + c * (CH/4) + tx];
        Hjs4[ty * (STR/4) + tx]        = Hj4[ty * (Dc/4) + c * (CH/4) + tx];
        Hjs4[(ty+16) * (STR/4) + tx]   = Hj4[(ty+16) * (Dc/4) + c * (CH/4) + tx];
        __syncthreads();

        const float4* hiA = (const float4*)(His + (size_t)ty * STR);
        const float4* hiB = (const float4*)(His + (size_t)(ty + 16) * STR);
        const float4* hjA = (const float4*)(Hjs + (size_t)tx * STR);
        const float4* hjB = (const float4*)(Hjs + (size_t)(tx + 16) * STR);
        const float4* w4  = (const float4*)(ws + c * CH);

#pragma unroll
        for (int g = 0; g < CH / 4; g++) {
            const float4 wv = w4[g];
            const float4 hp = hiA[g];
            const float4 hq = hiB[g];
            const float4 gu = hjA[g];
            const float4 gv = hjB[g];

            a00 = fmaf(tanh_fast(hp.x + gu.x), wv.x, a00);
            a01 = fmaf(tanh_fast(hp.x + gv.x), wv.x, a01);
            a10 = fmaf(tanh_fast(hq.x + gu.x), wv.x, a10);
            a11 = fmaf(tanh_fast(hq.x + gv.x), wv.x, a11);

            a00 = fmaf(tanh_fast(hp.y + gu.y), wv.y, a00);
            a01 = fmaf(tanh_fast(hp.y + gv.y), wv.y, a01);
            a10 = fmaf(tanh_fast(hq.y + gu.y), wv.y, a10);
            a11 = fmaf(tanh_fast(hq.y + gv.y), wv.y, a11);

            a00 = fmaf(tanh_fast(hp.z + gu.z), wv.z, a00);
            a01 = fmaf(tanh_fast(hp.z + gv.z), wv.z, a01);
            a10 = fmaf(tanh_fast(hq.z + gu.z), wv.z, a10);
            a11 = fmaf(tanh_fast(hq.z + gv.z), wv.z, a11);

            a00 = fmaf(tanh_fast(hp.w + gu.w), wv.w, a00);
            a01 = fmaf(tanh_fast(hp.w + gv.w), wv.w, a01);
            a10 = fmaf(tanh_fast(hq.w + gu.w), wv.w, a10);
            a11 = fmaf(tanh_fast(hq.w + gv.w), wv.w, a11);
        }
    }

    const float bias = *bias_p;
    a00 += bias; a01 += bias; a10 += bias; a11 += bias;

    const int gi0 = ti * TILE + ty, gi1 = gi0 + 16;
    const int gj0 = tj * TILE + tx, gj1 = gj0 + 16;
    float* Sb = Sbuf + (size_t)b * Lc * Lc;

    Sb[(size_t)gi0 * Lc + gj0] = a00;
    Sb[(size_t)gi0 * Lc + gj1] = a01;
    Sb[(size_t)gi1 * Lc + gj0] = a10;
    Sb[(size_t)gi1 * Lc + gj1] = a11;
    if (ti != tj) {
        Sb[(size_t)gj0 * Lc + gi0] = a00;
        Sb[(size_t)gj1 * Lc + gi0] = a01;
        Sb[(size_t)gj0 * Lc + gi1] = a10;
        Sb[(size_t)gj1 * Lc + gi1] = a11;
    }
}

// ---------------------------------------------------------------------------
// Kernel 2 (fused): row softmax (from Sbuf) + r = alpha @ H with FFMA2
// (fma.rn.f32x2) inner loop, cp.async H staging, j-split x2 with atomic
// accumulation into pre-zeroed R. Only js==0 writes normalized alpha.
// Block: 256 thr; 16 i-rows; thread (ig=tid>>5, dg=tid&31) owns rows
// {2ig, 2ig+1} and d in {2dg, 2dg+1} + k*64 (4 f32x2 pairs per row).
// ---------------------------------------------------------------------------
constexpr int ITR  = 16;               // rows per block
constexpr int JSP  = 2;                // j splits
constexpr int JBLK = Lc / JSP;         // 256
constexpr int JC   = 32;               // j rows per H chunk
constexpr int NCHK = JBLK / JC;        // 8
constexpr int SMEM_R = (ITR * Lc + 2 * JC * Dc) * (int)sizeof(float); // 98304

__global__ __launch_bounds__(256) void softmax_r_kernel(
    float* __restrict__ Alpha, const float* __restrict__ H,
    float* __restrict__ R)
{
    extern __shared__ float sh[];
    float* As  = sh;                    // 16 * 512
    float* Hs0 = sh + ITR * Lc;         // 32 * 256
    float* Hs1 = Hs0 + JC * Dc;         // 32 * 256

    const int blk   = blockIdx.x;
    const int js    = blk & 1;
    const int itile = (blk >> 1) & 31;
    const int b     = blk >> 6;
    const int tid   = threadIdx.x;
    const int warp  = tid >> 5;
    const int lane  = tid & 31;

    const float* Hb = H + (size_t)b * Lc * Dc + (size_t)js * JBLK * Dc;

    // Prefetch H chunk 0 while doing softmax.
#pragma unroll
    for (int k = 0; k < 8; k++) {
        const int v = tid + (k << 8);
        cp16(Hs0 + v * 4, Hb + (size_t)v * 4);
    }
    asm volatile("cp.async.commit_group;");

    // ---- softmax: warp handles rows 2*warp, 2*warp+1 (full 512-j rows) ----
    const float* Sb = Sbuf + ((size_t)b * Lc + (size_t)itile * ITR) * Lc;
    float* Ab = Alpha + ((size_t)b * Lc + (size_t)itile * ITR) * Lc;

#pragma unroll
    for (int rr = 0; rr < 2; rr++) {
        const int row = 2 * warp + rr;
        const float4* rg = (const float4*)(Sb + (size_t)row * Lc);
        float4* rs = (float4*)(As + (size_t)row * Lc);

        float4 v[4];
        float m = -3.0e38f;
#pragma unroll
        for (int t = 0; t < 4; t++) {
            v[t] = rg[lane + 32 * t];
            m = fmaxf(m, fmaxf(fmaxf(v[t].x, v[t].y), fmaxf(v[t].z, v[t].w)));
        }
#pragma unroll
        for (int o = 16; o > 0; o >>= 1)
            m = fmaxf(m, __shfl_xor_sync(0xffffffffu, m, o));

        float s = 0.f;
#pragma unroll
        for (int t = 0; t < 4; t++) {
            v[t].x = __expf(v[t].x - m);
            v[t].y = __expf(v[t].y - m);
            v[t].z = __expf(v[t].z - m);
            v[t].w = __expf(v[t].w - m);
            s += (v[t].x + v[t].y) + (v[t].z + v[t].w);
        }
#pragma unroll
        for (int o = 16; o > 0; o >>= 1)
            s += __shfl_xor_sync(0xffffffffu, s, o);

        const float inv = 1.0f / s;
#pragma unroll
        for (int t = 0; t < 4; t++) {
            v[t].x *= inv; v[t].y *= inv; v[t].z *= inv; v[t].w *= inv;
            rs[lane + 32 * t] = v[t];
        }
        if (js == 0) {
            float4* ag = (float4*)(Ab + (size_t)row * Lc);
#pragma unroll
            for (int t = 0; t < 4; t++)
                ag[lane + 32 * t] = v[t];
        }
    }

    // ---- FFMA2 GEMM over this block's j half ----
    const int ig = tid >> 5;   // row group: rows 2ig, 2ig+1
    const int dg = tid & 31;   // d base pair = 2*dg (+ k*64)

    u64 acc[2][4];
#pragma unroll
    for (int r = 0; r < 2; r++)
#pragma unroll
        for (int q = 0; q < 4; q++) acc[r][q] = 0ull;

    for (int c = 0; c < NCHK; c++) {
        float* cur = (c & 1) ? Hs1 : Hs0;
        float* nxt = (c & 1) ? Hs0 : Hs1;

        if (c < NCHK - 1) {
            const float* src = Hb + (size_t)(c + 1) * JC * Dc;
#pragma unroll
            for (int k = 0; k < 8; k++) {
                const int vv = tid + (k << 8);
                cp16(nxt + vv * 4, src + (size_t)vv * 4);
            }
            asm volatile("cp.async.commit_group;");
            asm volatile("cp.async.wait_group 1;");
        } else {
            asm volatile("cp.async.wait_group 0;");
        }
        __syncthreads();   // chunk visible; first iter also guards As

        const float* a0p = As + (size_t)(2 * ig) * Lc + js * JBLK + c * JC;
        const float* a1p = a0p + Lc;

#pragma unroll 8
        for (int jj = 0; jj < JC; jj++) {
            const float* hrow = cur + jj * Dc + 2 * dg;
            const u64 h0 = *(const u64*)(hrow);
            const u64 h1 = *(const u64*)(hrow + 64);
            const u64 h2 = *(const u64*)(hrow + 128);
            const u64 h3 = *(const u64*)(hrow + 192);

            const float al0 = a0p[jj];
            const float al1 = a1p[jj];
            u64 a20, a21;
            SPLAT2(a20, al0);
            SPLAT2(a21, al1);

            FMA2(acc[0][0], h0, a20, acc[0][0]);
            FMA2(acc[0][1], h1, a20, acc[0][1]);
            FMA2(acc[0][2], h2, a20, acc[0][2]);
            FMA2(acc[0][3], h3, a20, acc[0][3]);
            FMA2(acc[1][0], h0, a21, acc[1][0]);
            FMA2(acc[1][1], h1, a21, acc[1][1]);
            FMA2(acc[1][2], h2, a21, acc[1][2]);
            FMA2(acc[1][3], h3, a21, acc[1][3]);
        }
        __syncthreads();   // all warps done with 'cur' before refill
    }

    // ---- accumulate partial r (exactly 2 commutative adds onto 0) ----
    float* Rb = R + ((size_t)b * Lc + (size_t)itile * ITR) * Dc;
#pragma unroll
    for (int r = 0; r < 2; r++) {
        float* Rr = Rb + (size_t)(2 * ig + r) * Dc + 2 * dg;
#pragma unroll
        for (int q = 0; q < 4; q++) {
            float lo, hi;
            UNPACK2(lo, hi, acc[r][q]);
            atomicAdd(Rr + 64 * q,     lo);
            atomicAdd(Rr + 64 * q + 1, hi);
        }
    }
}

// ---------------------------------------------------------------------------
extern "C" void kernel_launch(void* const* d_in, const int* in_sizes, int n_in,
                              void* d_out, int out_size)
{
    const float* H    = (const float*)d_in[0];
    const float* w    = (const float*)d_in[1];
    const float* bias = (const float*)d_in[2];

    float* R     = (float*)d_out;                          // (B, L, D)
    float* Alpha = (float*)d_out + (size_t)Bc * Lc * Dc;   // (B, L, L)

    cudaFuncSetAttribute(softmax_r_kernel,
                         cudaFuncAttributeMaxDynamicSharedMemorySize, SMEM_R);

    scores_kernel<<<Bc * NPAIR, 256>>>(H, w, bias, R);
    softmax_r_kernel<<<Bc * (Lc / ITR) * JSP, 256, SMEM_R>>>(Alpha, H, R);
}

// round 7
// speedup vs baseline: 1.2280x; 1.0180x over previous
#include <cuda_runtime.h>
#include <cstddef>

#define Bc 4
#define Lc 512
#define Dc 256

constexpr int TILE  = 32;
constexpr int NT    = Lc / TILE;          // 16
constexpr int NPAIR = NT * (NT + 1) / 2;  // 136
constexpr int CH    = 64;                 // d-chunk (scores)
constexpr int NCH   = Dc / CH;            // 4
constexpr int STR   = CH + 4;             // 68: conflict-free & float4-aligned

// E = exp(raw scores) scratch (4 MB) + per-row exp sums.
__device__ float Sbuf[(size_t)Bc * Lc * Lc];
__device__ float RowSum[Bc * Lc];

typedef unsigned long long u64;

__device__ __forceinline__ float tanh_fast(float x) {
    float y;
    asm("tanh.approx.f32 %0, %1;" : "=f"(y) : "f"(x));
    return y;
}

__device__ __forceinline__ void cp16(float* s, const float* g) {
    unsigned saddr = (unsigned)__cvta_generic_to_shared(s);
    asm volatile("cp.async.cg.shared.global [%0], [%1], 16;" :: "r"(saddr), "l"(g));
}

#define FMA2(d, a, b, c) \
    asm("fma.rn.f32x2 %0, %1, %2, %3;" : "=l"(d) : "l"(a), "l"(b), "l"(c))
#define SPLAT2(d, f) \
    asm("mov.b64 %0, {%1, %1};" : "=l"(d) : "f"(f))
#define UNPACK2(lo, hi, p) \
    asm("mov.b64 {%0, %1}, %2;" : "=f"(lo), "=f"(hi) : "l"(p))

// ---------------------------------------------------------------------------
// Kernel 0: zero RowSum (scores_kernel atomically accumulates into it).
// ---------------------------------------------------------------------------
__global__ void init_kernel()
{
    const int u = blockIdx.x * 256 + threadIdx.x;          // 512 float4
    ((float4*)RowSum)[u] = make_float4(0.f, 0.f, 0.f, 0.f);
}

// ---------------------------------------------------------------------------
// Kernel 1: pairwise tanh scores -> E = exp(score+bias) into Sbuf, with
// per-row exp-sums accumulated into RowSum (shuffle reduce + atomics).
// Symmetric tiles (ti <= tj) with mirror stores. Also zeroes R for the
// downstream atomic-accumulating GEMM.
// ---------------------------------------------------------------------------
__global__ __launch_bounds__(256) void scores_kernel(
    const float* __restrict__ H, const float* __restrict__ w,
    const float* __restrict__ bias_p, float* __restrict__ R)
{
    __shared__ float His[TILE * STR];
    __shared__ float Hjs[TILE * STR];
    __shared__ float ws[Dc];
    __shared__ float jsum[TILE];

    const int blk = blockIdx.x;
    const int tid = threadIdx.x;

    // Zero R (B*L*D floats = 131072 float4; grid is 544 >= 512 blocks).
    {
        const int u = blk * 256 + tid;
        if (u < (Bc * Lc * Dc) / 4)
            ((float4*)R)[u] = make_float4(0.f, 0.f, 0.f, 0.f);
    }
    if (tid < TILE) jsum[tid] = 0.f;

    const int b = blk / NPAIR;
    int p = blk % NPAIR;
    int ti = 0;
    while (p >= NT - ti) { p -= NT - ti; ti++; }
    const int tj = ti + p;

    ws[tid] = w[tid];

    const int ty = tid >> 4;   // 0..15
    const int tx = tid & 15;   // 0..15

    const float4* Hi4 = (const float4*)(H + ((size_t)b * Lc + (size_t)ti * TILE) * Dc);
    const float4* Hj4 = (const float4*)(H + ((size_t)b * Lc + (size_t)tj * TILE) * Dc);
    float4* His4 = (float4*)His;
    float4* Hjs4 = (float4*)Hjs;

    float a00 = 0.f, a01 = 0.f, a10 = 0.f, a11 = 0.f;

    for (int c = 0; c < NCH; c++) {
        __syncthreads();
        His4[ty * (STR/4) + tx]        = Hi4[ty * (Dc/4) + c * (CH/4) + tx];
        His4[(ty+16) * (STR/4) + tx]   = Hi4[(ty+16) * (Dc/4) + c * (CH/4) + tx];
        Hjs4[ty * (STR/4) + tx]        = Hj4[ty * (Dc/4) + c * (CH/4) + tx];
        Hjs4[(ty+16) * (STR/4) + tx]   = Hj4[(ty+16) * (Dc/4) + c * (CH/4) + tx];
        __syncthreads();

        const float4* hiA = (const float4*)(His + (size_t)ty * STR);
        const float4* hiB = (const float4*)(His + (size_t)(ty + 16) * STR);
        const float4* hjA = (const float4*)(Hjs + (size_t)tx * STR);
        const float4* hjB = (const float4*)(Hjs + (size_t)(tx + 16) * STR);
        const float4* w4  = (const float4*)(ws + c * CH);

#pragma unroll
        for (int g = 0; g < CH / 4; g++) {
            const float4 wv = w4[g];
            const float4 hp = hiA[g];
            const float4 hq = hiB[g];
            const float4 gu = hjA[g];
            const float4 gv = hjB[g];

            a00 = fmaf(tanh_fast(hp.x + gu.x), wv.x, a00);
            a01 = fmaf(tanh_fast(hp.x + gv.x), wv.x, a01);
            a10 = fmaf(tanh_fast(hq.x + gu.x), wv.x, a10);
            a11 = fmaf(tanh_fast(hq.x + gv.x), wv.x, a11);

            a00 = fmaf(tanh_fast(hp.y + gu.y), wv.y, a00);
            a01 = fmaf(tanh_fast(hp.y + gv.y), wv.y, a01);
            a10 = fmaf(tanh_fast(hq.y + gu.y), wv.y, a10);
            a11 = fmaf(tanh_fast(hq.y + gv.y), wv.y, a11);

            a00 = fmaf(tanh_fast(hp.z + gu.z), wv.z, a00);
            a01 = fmaf(tanh_fast(hp.z + gv.z), wv.z, a01);
            a10 = fmaf(tanh_fast(hq.z + gu.z), wv.z, a10);
            a11 = fmaf(tanh_fast(hq.z + gv.z), wv.z, a11);

            a00 = fmaf(tanh_fast(hp.w + gu.w), wv.w, a00);
            a01 = fmaf(tanh_fast(hp.w + gv.w), wv.w, a01);
            a10 = fmaf(tanh_fast(hq.w + gu.w), wv.w, a10);
            a11 = fmaf(tanh_fast(hq.w + gv.w), wv.w, a11);
        }
    }

    const float bias = *bias_p;
    const float e00 = __expf(a00 + bias);
    const float e01 = __expf(a01 + bias);
    const float e10 = __expf(a10 + bias);
    const float e11 = __expf(a11 + bias);

    const int gi0 = ti * TILE + ty, gi1 = gi0 + 16;
    const int gj0 = tj * TILE + tx, gj1 = gj0 + 16;
    float* Sb = Sbuf + (size_t)b * Lc * Lc;

    Sb[(size_t)gi0 * Lc + gj0] = e00;
    Sb[(size_t)gi0 * Lc + gj1] = e01;
    Sb[(size_t)gi1 * Lc + gj0] = e10;
    Sb[(size_t)gi1 * Lc + gj1] = e11;
    if (ti != tj) {
        Sb[(size_t)gj0 * Lc + gi0] = e00;
        Sb[(size_t)gj1 * Lc + gi0] = e01;
        Sb[(size_t)gj0 * Lc + gi1] = e10;
        Sb[(size_t)gj1 * Lc + gi1] = e11;
    }

    // ---- i-row sums over this tile's 32 j-columns ----
    float ri0 = e00 + e01;
    float ri1 = e10 + e11;
#pragma unroll
    for (int o = 1; o < 16; o <<= 1) {
        ri0 += __shfl_xor_sync(0xffffffffu, ri0, o);
        ri1 += __shfl_xor_sync(0xffffffffu, ri1, o);
    }
    if (tx == 0) {
        atomicAdd(&RowSum[b * Lc + gi0], ri0);
        atomicAdd(&RowSum[b * Lc + gi1], ri1);
    }

    // ---- mirrored j-row sums (skip on diagonal: same rows) ----
    if (ti != tj) {
        float cj0 = e00 + e10;
        float cj1 = e01 + e11;
        cj0 += __shfl_xor_sync(0xffffffffu, cj0, 16);  // fold the warp's 2 ty
        cj1 += __shfl_xor_sync(0xffffffffu, cj1, 16);
        if ((tid & 31) < 16) {
            atomicAdd(&jsum[tx], cj0);
            atomicAdd(&jsum[tx + 16], cj1);
        }
        __syncthreads();
        if (tid < TILE)
            atomicAdd(&RowSum[b * Lc + tj * TILE + tid], jsum[tid]);
    }
}

// ---------------------------------------------------------------------------
// Kernel 2: normalize E -> alpha (write out) + r = alpha @ H.
// Block: 256 thr / 8 warps, covers 64 i-rows x 256 d, j-range of 128 (js=4).
// Warp = 8-row group; lane owns d = {4*lane..+3} U {128+4*lane..+3}.
// Inner loop: 2 LDS.128 (H) + amortized LDS.128 alpha broadcasts feeding
// 32 fma.rn.f32x2 per jj -> FMA-pipe bound (crossbar at ~60%).
// Partial r accumulated into pre-zeroed R via atomicAdd.
// ---------------------------------------------------------------------------
constexpr int ITR  = 64;               // rows per block
constexpr int JSP  = 4;                // j splits
constexpr int JBLK = Lc / JSP;         // 128
constexpr int JC   = 32;               // j rows per H chunk
constexpr int NCHK = JBLK / JC;        // 4
constexpr int SMEM_R = (ITR * JBLK + 2 * JC * Dc + 64) * (int)sizeof(float);

__global__ __launch_bounds__(256) void softmax_r_kernel(
    float* __restrict__ Alpha, const float* __restrict__ H,
    float* __restrict__ R)
{
    extern __shared__ float sh[];
    float* As   = sh;                    // 64 x 128 (normalized alpha slice)
    float* Hs0  = sh + ITR * JBLK;       // 32 x 256
    float* Hs1  = Hs0 + JC * Dc;         // 32 x 256
    float* invs = Hs1 + JC * Dc;         // 64

    const int blk   = blockIdx.x;
    const int js    = blk & 3;
    const int itile = (blk >> 2) & 7;
    const int b     = blk >> 5;
    const int tid   = threadIdx.x;
    const int warp  = tid >> 5;
    const int lane  = tid & 31;

    const float* Hb = H + (size_t)b * Lc * Dc + (size_t)js * JBLK * Dc;

    // Prefetch H chunk 0.
#pragma unroll
    for (int k = 0; k < 8; k++) {
        const int v = tid + (k << 8);
        cp16(Hs0 + v * 4, Hb + (size_t)v * 4);
    }
    asm volatile("cp.async.commit_group;");

    if (tid < ITR)
        invs[tid] = 1.0f / RowSum[b * Lc + itile * ITR + tid];
    __syncthreads();

    // Stage normalized alpha slice: E * inv -> As (smem) and Alpha (global).
    const size_t rowbase = (size_t)b * Lc + (size_t)itile * ITR;
    const float4* E4 = (const float4*)Sbuf;
    float4* A4 = (float4*)Alpha;
    float4* As4 = (float4*)As;
#pragma unroll
    for (int it = 0; it < 8; it++) {
        const int idx = tid + (it << 8);     // 0..2047
        const int row = idx >> 5;
        const int j4  = idx & 31;
        const size_t g = (rowbase + row) * (Lc / 4) + js * (JBLK / 4) + j4;
        float4 e = E4[g];
        const float iv = invs[row];
        e.x *= iv; e.y *= iv; e.z *= iv; e.w *= iv;
        As4[row * (JBLK / 4) + j4] = e;
        A4[g] = e;
    }

    // ---- FFMA2 GEMM over this block's j range ----
    u64 acc[8][4];
#pragma unroll
    for (int r = 0; r < 8; r++)
#pragma unroll
        for (int q = 0; q < 4; q++) acc[r][q] = 0ull;

    for (int c = 0; c < NCHK; c++) {
        float* cur = (c & 1) ? Hs1 : Hs0;
        float* nxt = (c & 1) ? Hs0 : Hs1;

        if (c < NCHK - 1) {
            const float* src = Hb + (size_t)(c + 1) * JC * Dc;
#pragma unroll
            for (int k = 0; k < 8; k++) {
                const int vv = tid + (k << 8);
                cp16(nxt + vv * 4, src + (size_t)vv * 4);
            }
            asm volatile("cp.async.commit_group;");
            asm volatile("cp.async.wait_group 1;");
        } else {
            asm volatile("cp.async.wait_group 0;");
        }
        __syncthreads();   // chunk visible; first iter also guards As

#pragma unroll
        for (int jg = 0; jg < JC / 4; jg++) {
            // alpha for 4 j's x 8 rows (broadcast LDS.128)
            float4 a[8];
#pragma unroll
            for (int r = 0; r < 8; r++)
                a[r] = *(const float4*)(As + (size_t)(warp * 8 + r) * JBLK
                                        + c * JC + jg * 4);
#pragma unroll
            for (int u = 0; u < 4; u++) {
                const float* hp = cur + (jg * 4 + u) * Dc + 4 * lane;
                const ulonglong2 hlo = *(const ulonglong2*)(hp);
                const ulonglong2 hhi = *(const ulonglong2*)(hp + 128);
#pragma unroll
                for (int r = 0; r < 8; r++) {
                    const float av = (u == 0) ? a[r].x : (u == 1) ? a[r].y
                                   : (u == 2) ? a[r].z : a[r].w;
                    u64 s;
                    SPLAT2(s, av);
                    FMA2(acc[r][0], hlo.x, s, acc[r][0]);
                    FMA2(acc[r][1], hlo.y, s, acc[r][1]);
                    FMA2(acc[r][2], hhi.x, s, acc[r][2]);
                    FMA2(acc[r][3], hhi.y, s, acc[r][3]);
                }
            }
        }
        __syncthreads();   // all warps done with 'cur' before refill
    }

    // ---- accumulate partials (JSP commutative adds onto zeroed R) ----
#pragma unroll
    for (int r = 0; r < 8; r++) {
        float* Rr = R + (rowbase + warp * 8 + r) * Dc;
#pragma unroll
        for (int q = 0; q < 4; q++) {
            const int d = (q < 2) ? (4 * lane + 2 * q) : (128 + 4 * lane + 2 * (q - 2));
            float lo, hi;
            UNPACK2(lo, hi, acc[r][q]);
            atomicAdd(Rr + d,     lo);
            atomicAdd(Rr + d + 1, hi);
        }
    }
}

// ---------------------------------------------------------------------------
extern "C" void kernel_launch(void* const* d_in, const int* in_sizes, int n_in,
                              void* d_out, int out_size)
{
    const float* H    = (const float*)d_in[0];
    const float* w    = (const float*)d_in[1];
    const float* bias = (const float*)d_in[2];

    float* R     = (float*)d_out;                          // (B, L, D)
    float* Alpha = (float*)d_out + (size_t)Bc * Lc * Dc;   // (B, L, L)

    cudaFuncSetAttribute(softmax_r_kernel,
                         cudaFuncAttributeMaxDynamicSharedMemorySize, SMEM_R);

    init_kernel<<<2, 256>>>();
    scores_kernel<<<Bc * NPAIR, 256>>>(H, w, bias, R);
    softmax_r_kernel<<<Bc * (Lc / ITR) * JSP, 256, SMEM_R>>>(Alpha, H, R);
}